// round 6
// baseline (speedup 1.0000x reference)
#include <cuda_runtime.h>
#include <math.h>

#define T    128
#define D    64
#define H    256
#define HK   128
#define DD   (D*D)
#define ITERS 3
#define NB   128
#define NT   512
#define NSLOT (NB*4)

// ---- scratch (static device globals; no runtime allocation) ----
__device__ float A_g[T*T*HK];          // 8 MB  A[i][j*HK+h] = w_ij * tanh(...)
__device__ float W2T_g[HK*DD];         // 2 MB  Wk2 transposed per-row: [h][e][d]
__device__ float bk2T_g[DD];           //       bk2 transposed: [e][d]
__device__ float fyT_g[D*T];           //       f(y) transposed: [e][j]
__device__ float c_g[T*D];
__device__ float M3_g[T*HK*D];         // 4 MB
__device__ float Gpart_g[NSLOT*T*D];   // 16 MB (512 deterministic slots)
__device__ float G_g[T*D];

// grid barrier: arrive/depart pair per instance; last departer resets both,
// so every launch / graph replay starts from zeroed counters.
__device__ unsigned bar_arr[16];
__device__ unsigned bar_dep[16];

__device__ __forceinline__ void gsync(int b) {
    __threadfence();
    __syncthreads();
    if (threadIdx.x == 0) {
        atomicAdd(&bar_arr[b], 1u);
        while (*(volatile unsigned*)&bar_arr[b] < NB) { }
        __threadfence();
        unsigned o = atomicAdd(&bar_dep[b], 1u);
        if (o == NB - 1) {
            *(volatile unsigned*)&bar_arr[b] = 0u;
            *(volatile unsigned*)&bar_dep[b] = 0u;
        }
    }
    __syncthreads();
}

// trapezoid weight w[i][j]: w = dt*(j<=i); w[i,i]*=0.5; w[:,0]*=0.5; w[0,:]=0
__device__ __forceinline__ float wfun(int i, int j, float dt) {
    if (i == 0 || j > i) return 0.0f;
    float v = dt;
    if (j == i) v *= 0.5f;
    if (j == 0) v *= 0.5f;
    return v;
}

__global__ void __launch_bounds__(NT, 1) mega(
    const float* __restrict__ z0, const float* __restrict__ t,
    const float* __restrict__ W1, const float* __restrict__ b1,
    const float* __restrict__ W2, const float* __restrict__ b2,
    const float* __restrict__ Wk1, const float* __restrict__ bk1,
    const float* __restrict__ Wk2, const float* __restrict__ bk2,
    float* __restrict__ out)
{
    extern __shared__ float sbuf[];              // 48 KB dynamic, multipurpose
    __shared__ float wa[HK], wb[HK], bkk[HK], ts[T];
    __shared__ float yrow[D], hid[H], fyr[D];
    __shared__ float part8[8][D];
    __shared__ float hidpart[2][H];

    int bid = blockIdx.x, tid = threadIdx.x;

    // ================= SETUP =================
    // W2T[h=bid][e][d] = Wk2[h][d*64+e]
    #pragma unroll
    for (int r = 0; r < 8; r++) {
        int idx = tid + r * 512;
        sbuf[(idx >> 6) * 67 + (idx & 63)] = Wk2[bid * DD + idx];
    }
    __syncthreads();
    #pragma unroll
    for (int r = 0; r < 8; r++) {
        int idx = tid + r * 512;
        W2T_g[bid * DD + idx] = sbuf[(idx & 63) * 67 + (idx >> 6)];
    }
    __syncthreads();
    if (bid == 0) {            // bk2T (block-uniform branch; syncthreads legal)
        #pragma unroll
        for (int r = 0; r < 8; r++) {
            int idx = tid + r * 512;
            sbuf[(idx >> 6) * 67 + (idx & 63)] = bk2[idx];
        }
        __syncthreads();
        #pragma unroll
        for (int r = 0; r < 8; r++) {
            int idx = tid + r * 512;
            bk2T_g[idx] = sbuf[(idx & 63) * 67 + (idx >> 6)];
        }
    }
    if (tid < HK) { wa[tid] = Wk1[tid]; wb[tid] = Wk1[HK + tid]; bkk[tid] = bk1[tid]; }
    if (tid < T)  ts[tid] = t[tid];
    __syncthreads();
    float dt = ts[1] - ts[0];
    {
        float ti = ts[bid];
        #pragma unroll 4
        for (int r = 0; r < 32; r++) {
            int idx = tid + r * 512;
            int j = idx >> 7, h = idx & 127;
            float v = tanhf(ti * wa[h] + ts[j] * wb[h] + bkk[h]);
            A_g[bid * (T * HK) + idx] = wfun(bid, j, dt) * v;
        }
    }

    int bar = 0;
    gsync(bar++);

    // ================= FIXED-POINT ITERATIONS =================
    for (int it = 0; it < ITERS; it++) {
        // ---- phase F (block j): y_j = y0 + (w@G)_j (fused), then fy[j], c[j] ----
        {
            int j = bid;
            int d = tid & 63, p = tid >> 6;        // 8-way split
            if (it == 0) {
                if (tid < D) yrow[tid] = z0[tid];
            } else {
                float s = 0.0f;
                for (int i = p; i <= j; i += 8)
                    s += wfun(j, i, dt) * __ldcg(&G_g[i * D + d]);
                part8[p][d] = s;
                __syncthreads();
                if (p == 0)
                    yrow[d] = z0[d] + part8[0][d] + part8[1][d] + part8[2][d] + part8[3][d]
                                    + part8[4][d] + part8[5][d] + part8[6][d] + part8[7][d];
            }
            __syncthreads();
            // hidden: (h, q) q=2-way split over e
            {
                int h = tid & 255, q = tid >> 8;
                float s = (q == 0) ? b1[h] : 0.0f;
                #pragma unroll
                for (int ee = 0; ee < 32; ee++) {
                    int e = q * 32 + ee;
                    s += yrow[e] * W1[e * H + h];
                }
                hidpart[q][h] = s;
            }
            __syncthreads();
            if (tid < H) hid[tid] = tanhf(hidpart[0][tid] + hidpart[1][tid]);
            __syncthreads();
            // fy: 8-way split over h (32 each)
            {
                float s = 0.0f;
                #pragma unroll
                for (int hh = 0; hh < 32; hh++) {
                    int h = p * 32 + hh;
                    s += hid[h] * W2[h * D + d];
                }
                part8[p][d] = s;
            }
            __syncthreads();
            if (p == 0) {
                float f = b2[d] + part8[0][d] + part8[1][d] + part8[2][d] + part8[3][d]
                                + part8[4][d] + part8[5][d] + part8[6][d] + part8[7][d];
                fyr[d] = f;
                fyT_g[d * T + j] = f;              // transposed [e][j]
            }
            __syncthreads();
            // c: 8-way split over e (8 each)
            {
                float s = 0.0f;
                #pragma unroll
                for (int ee = 0; ee < 8; ee++) {
                    int e = p * 8 + ee;
                    s += bk2T_g[e * D + d] * fyr[e];
                }
                part8[p][d] = s;
            }
            __syncthreads();
            if (p == 0)
                c_g[j * D + d] = part8[0][d] + part8[1][d] + part8[2][d] + part8[3][d]
                               + part8[4][d] + part8[5][d] + part8[6][d] + part8[7][d];
        }
        gsync(bar++);

        // ---- phase M3 (block h): M3[(j,h)][d] = sum_e W2T[h][e][d] * fy[j][e] ----
        // one pass over all 128 j; 4x4 register tile; float4 on both operands.
        {
            int h = bid;
            float* w2s  = sbuf;            // [e][d]  4096
            float* fyTs = sbuf + 4096;     // [e][j]  8192
            #pragma unroll
            for (int r = 0; r < 8; r++)
                w2s[tid + r * 512] = W2T_g[h * DD + tid + r * 512];
            #pragma unroll
            for (int r = 0; r < 16; r++)
                fyTs[tid + r * 512] = __ldcg(&fyT_g[tid + r * 512]);
            __syncthreads();
            int tx = tid & 15, ty = tid >> 4;   // tx: 4 d, ty: 4 j (32*4=128)
            float acc[4][4] = {};
            #pragma unroll
            for (int e = 0; e < D; e++) {
                float4 wv = *(const float4*)&w2s[e * 64 + tx * 4];
                float4 fv = *(const float4*)&fyTs[e * 128 + ty * 4];
                acc[0][0] += fv.x * wv.x; acc[0][1] += fv.x * wv.y;
                acc[0][2] += fv.x * wv.z; acc[0][3] += fv.x * wv.w;
                acc[1][0] += fv.y * wv.x; acc[1][1] += fv.y * wv.y;
                acc[1][2] += fv.y * wv.z; acc[1][3] += fv.y * wv.w;
                acc[2][0] += fv.z * wv.x; acc[2][1] += fv.z * wv.y;
                acc[2][2] += fv.z * wv.z; acc[2][3] += fv.z * wv.w;
                acc[3][0] += fv.w * wv.x; acc[3][1] += fv.w * wv.y;
                acc[3][2] += fv.w * wv.z; acc[3][3] += fv.w * wv.w;
            }
            #pragma unroll
            for (int jl = 0; jl < 4; jl++) {
                int j = ty * 4 + jl;
                float4 o = make_float4(acc[jl][0], acc[jl][1], acc[jl][2], acc[jl][3]);
                __stcg((float4*)&M3_g[(j * HK + h) * D + tx * 4], o);
            }
        }
        gsync(bar++);

        // ---- phase G: 4 groups x 128 threads; group g: (j, 32-wide h-slice) ----
        // g0,g1: j=bid h[0:32),[32:64); g2,g3: j=127-bid h[64:96),[96:128)
        // 8x8 register tiles -> 96 B/cyc smem demand (under the 128 B/cyc limit)
        {
            int g  = tid >> 7;             // 0..3
            int tg = tid & 127;
            int txg = tg & 7, tyg = tg >> 3;        // 8 d cols, 8 i rows each
            int jj   = (g < 2) ? bid : (127 - bid);
            int jbase = jj * HK + g * 32;
            float* As = sbuf + g * 1536;   // [hh][i] 8x128
            float* Bs = As + 1024;         // [hh][d] 8x64
            float acc[8][8] = {};
            bool active = (tyg * 8 + 7) >= jj;
            #pragma unroll
            for (int kb = 0; kb < 4; kb++) {
                __syncthreads();
                const float* ap = &A_g[tg * (T * HK) + jbase + kb * 8];
                float4 v0 = *(const float4*)ap;
                float4 v1 = *(const float4*)(ap + 4);
                As[0 * 128 + tg] = v0.x;  As[1 * 128 + tg] = v0.y;
                As[2 * 128 + tg] = v0.z;  As[3 * 128 + tg] = v0.w;
                As[4 * 128 + tg] = v1.x;  As[5 * 128 + tg] = v1.y;
                As[6 * 128 + tg] = v1.z;  As[7 * 128 + tg] = v1.w;
                ((float4*)Bs)[tg] = __ldcg(((const float4*)&M3_g[(jbase + kb * 8) * D]) + tg);
                __syncthreads();
                if (active) {
                    #pragma unroll
                    for (int hh = 0; hh < 8; hh++) {
                        float4 a0 = *(const float4*)&As[hh * 128 + tyg * 8];
                        float4 a1 = *(const float4*)&As[hh * 128 + tyg * 8 + 4];
                        float4 b0 = *(const float4*)&Bs[hh * 64 + txg * 8];
                        float4 b1 = *(const float4*)&Bs[hh * 64 + txg * 8 + 4];
                        float a[8] = {a0.x, a0.y, a0.z, a0.w, a1.x, a1.y, a1.z, a1.w};
                        float b[8] = {b0.x, b0.y, b0.z, b0.w, b1.x, b1.y, b1.z, b1.w};
                        #pragma unroll
                        for (int r = 0; r < 8; r++)
                            #pragma unroll
                            for (int cc = 0; cc < 8; cc++)
                                acc[r][cc] += a[r] * b[cc];
                    }
                }
            }
            float* gp = &Gpart_g[(bid * 4 + g) * (T * D)];
            #pragma unroll
            for (int r = 0; r < 8; r++) {
                float4 o0 = make_float4(acc[r][0], acc[r][1], acc[r][2], acc[r][3]);
                float4 o1 = make_float4(acc[r][4], acc[r][5], acc[r][6], acc[r][7]);
                *(float4*)&gp[(tyg * 8 + r) * D + txg * 8]     = o0;
                *(float4*)&gp[(tyg * 8 + r) * D + txg * 8 + 4] = o1;
            }
        }
        gsync(bar++);

        // ---- phase R (block i): reduce 512 partials + bias quadrature -> G ----
        {
            int i = bid;
            int d = tid & 63, p = tid >> 6;
            float s = 0.0f;
            #pragma unroll 8
            for (int slot = p; slot < NSLOT; slot += 8)
                s += __ldcg(&Gpart_g[slot * (T * D) + i * D + d]);
            for (int j = p; j <= i; j += 8)
                s += wfun(i, j, dt) * __ldcg(&c_g[j * D + d]);
            part8[p][d] = s;
            __syncthreads();
            if (p == 0)
                G_g[i * D + d] = part8[0][d] + part8[1][d] + part8[2][d] + part8[3][d]
                               + part8[4][d] + part8[5][d] + part8[6][d] + part8[7][d];
        }
        gsync(bar++);
    }

    // ---- tail: block 127 computes out = y0 + (w@G)_{127} ----
    if (bid == T - 1) {
        int d = tid & 63, p = tid >> 6;
        float s = 0.0f;
        for (int i = p; i < T; i += 8)
            s += wfun(T - 1, i, dt) * __ldcg(&G_g[i * D + d]);
        part8[p][d] = s;
        __syncthreads();
        if (p == 0)
            out[d] = z0[d] + part8[0][d] + part8[1][d] + part8[2][d] + part8[3][d]
                           + part8[4][d] + part8[5][d] + part8[6][d] + part8[7][d];
    }
}

extern "C" void kernel_launch(void* const* d_in, const int* in_sizes, int n_in,
                              void* d_out, int out_size) {
    const float* z0  = (const float*)d_in[0];
    const float* t   = (const float*)d_in[1];
    const float* W1  = (const float*)d_in[2];
    const float* b1  = (const float*)d_in[3];
    const float* W2  = (const float*)d_in[4];
    const float* b2  = (const float*)d_in[5];
    const float* Wk1 = (const float*)d_in[6];
    const float* bk1 = (const float*)d_in[7];
    const float* Wk2 = (const float*)d_in[8];
    const float* bk2 = (const float*)d_in[9];
    float* out = (float*)d_out;

    static int attr_done = 0;
    if (!attr_done) {
        cudaFuncSetAttribute(mega, cudaFuncAttributeMaxDynamicSharedMemorySize, 64 * 1024);
        attr_done = 1;
    }
    mega<<<NB, NT, 49152>>>(z0, t, W1, b1, W2, b2, Wk1, bk1, Wk2, bk2, out);
}

// round 7
// speedup vs baseline: 1.0943x; 1.0943x over previous
#include <cuda_runtime.h>
#include <math.h>

#define T    128
#define D    64
#define H    256
#define HK   128
#define DD   (D*D)
#define ITERS 3
#define NB   128
#define NT   512
#define NBAR 16
#define NLEAF 16

// ---- scratch (static device globals; no runtime allocation) ----
__device__ float AT_g[T*HK*T];         // 8 MB  AT[(j*HK+h)][i] = w_ij * tanh(...)
__device__ float W2T_g[HK*DD];         // 2 MB  Wk2 transposed per-row: [h][e][d]
__device__ float bk2T_g[DD];           //       bk2 transposed: [e][d]
__device__ float fyT_g[D*T];           //       f(y) transposed: [e][j]
__device__ float c_g[T*D];
__device__ float M3_g[T*HK*D];         // 4 MB
__device__ float Gpart_g[NB*T*D];      // 4 MB  (one slot per block)
__device__ float G_g[T*D];

// hierarchical grid barrier: 16 leaves x 8 blocks; hierarchical arrive+depart;
// last root-departer resets everything -> safe across graph replays.
__device__ unsigned lfA[NBAR][NLEAF];
__device__ unsigned rtA[NBAR];
__device__ unsigned lfD[NBAR][NLEAF];
__device__ unsigned rtD[NBAR];

__device__ __forceinline__ void gsync(int b) {
    __syncthreads();
    if (threadIdx.x == 0) {
        __threadfence();
        int leaf = blockIdx.x & (NLEAF - 1);
        if (atomicAdd(&lfA[b][leaf], 1u) == 7u)
            atomicAdd(&rtA[b], 1u);
        while (*(volatile unsigned*)&rtA[b] < (unsigned)NLEAF) { }
        __threadfence();
        if (atomicAdd(&lfD[b][leaf], 1u) == 7u) {
            if (atomicAdd(&rtD[b], 1u) == (unsigned)(NLEAF - 1)) {
                #pragma unroll
                for (int l = 0; l < NLEAF; l++) { lfA[b][l] = 0u; lfD[b][l] = 0u; }
                rtA[b] = 0u;
                __threadfence();
                rtD[b] = 0u;
            }
        }
    }
    __syncthreads();
}

// trapezoid weight w[i][j]: w = dt*(j<=i); w[i,i]*=0.5; w[:,0]*=0.5; w[0,:]=0
__device__ __forceinline__ float wfun(int i, int j, float dt) {
    if (i == 0 || j > i) return 0.0f;
    float v = dt;
    if (j == i) v *= 0.5f;
    if (j == 0) v *= 0.5f;
    return v;
}

__global__ void __launch_bounds__(NT, 1) mega(
    const float* __restrict__ z0, const float* __restrict__ t,
    const float* __restrict__ W1, const float* __restrict__ b1,
    const float* __restrict__ W2, const float* __restrict__ b2,
    const float* __restrict__ Wk1, const float* __restrict__ bk1,
    const float* __restrict__ Wk2, const float* __restrict__ bk2,
    float* __restrict__ out)
{
    extern __shared__ float sbuf[];              // 48 KB dynamic, multipurpose
    __shared__ float wa[HK], wb[HK], bkk[HK], ts[T];
    __shared__ float yrow[D], hid[H], fyr[D];
    __shared__ float part8[8][D];
    __shared__ float hidpart[2][H];

    int bid = blockIdx.x, tid = threadIdx.x;

    // ================= SETUP =================
    // W2T[h=bid][e][d] = Wk2[h][d*64+e]
    #pragma unroll
    for (int r = 0; r < 8; r++) {
        int idx = tid + r * 512;
        sbuf[(idx >> 6) * 67 + (idx & 63)] = Wk2[bid * DD + idx];
    }
    __syncthreads();
    #pragma unroll
    for (int r = 0; r < 8; r++) {
        int idx = tid + r * 512;
        W2T_g[bid * DD + idx] = sbuf[(idx & 63) * 67 + (idx >> 6)];
    }
    __syncthreads();
    if (bid == 0) {            // bk2T (block-uniform branch; syncthreads legal)
        #pragma unroll
        for (int r = 0; r < 8; r++) {
            int idx = tid + r * 512;
            sbuf[(idx >> 6) * 67 + (idx & 63)] = bk2[idx];
        }
        __syncthreads();
        #pragma unroll
        for (int r = 0; r < 8; r++) {
            int idx = tid + r * 512;
            bk2T_g[idx] = sbuf[(idx & 63) * 67 + (idx >> 6)];
        }
    }
    if (tid < HK) { wa[tid] = Wk1[tid]; wb[tid] = Wk1[HK + tid]; bkk[tid] = bk1[tid]; }
    if (tid < T)  ts[tid] = t[tid];
    __syncthreads();
    float dt = ts[1] - ts[0];
    // AT[(j=bid)*HK + h][i]  -- writes coalesced over i
    {
        int j = bid;
        float tj = ts[j];
        #pragma unroll 4
        for (int r = 0; r < 32; r++) {
            int idx = tid + r * 512;               // 0..16383
            int h = idx >> 7, i = idx & 127;
            float v = tanhf(ts[i] * wa[h] + tj * wb[h] + bkk[h]);
            AT_g[j * (HK * T) + idx] = wfun(i, j, dt) * v;
        }
    }

    int bar = 0;
    gsync(bar++);

    // ================= FIXED-POINT ITERATIONS =================
    for (int it = 0; it < ITERS; it++) {
        // ---- phase F (block j): y_j = y0 + (w@G)_j (fused), then fy[j], c[j] ----
        {
            int j = bid;
            int d = tid & 63, p = tid >> 6;        // 8-way split
            if (it == 0) {
                if (tid < D) yrow[tid] = z0[tid];
            } else {
                float s = 0.0f;
                for (int i = p; i <= j; i += 8)
                    s += wfun(j, i, dt) * __ldcg(&G_g[i * D + d]);
                part8[p][d] = s;
                __syncthreads();
                if (p == 0)
                    yrow[d] = z0[d] + part8[0][d] + part8[1][d] + part8[2][d] + part8[3][d]
                                    + part8[4][d] + part8[5][d] + part8[6][d] + part8[7][d];
            }
            __syncthreads();
            // hidden: (h, q) q=2-way split over e
            {
                int h = tid & 255, q = tid >> 8;
                float s = (q == 0) ? b1[h] : 0.0f;
                #pragma unroll
                for (int ee = 0; ee < 32; ee++) {
                    int e = q * 32 + ee;
                    s += yrow[e] * W1[e * H + h];
                }
                hidpart[q][h] = s;
            }
            __syncthreads();
            if (tid < H) hid[tid] = tanhf(hidpart[0][tid] + hidpart[1][tid]);
            __syncthreads();
            // fy: 8-way split over h (32 each)
            {
                float s = 0.0f;
                #pragma unroll
                for (int hh = 0; hh < 32; hh++) {
                    int h = p * 32 + hh;
                    s += hid[h] * W2[h * D + d];
                }
                part8[p][d] = s;
            }
            __syncthreads();
            if (p == 0) {
                float f = b2[d] + part8[0][d] + part8[1][d] + part8[2][d] + part8[3][d]
                                + part8[4][d] + part8[5][d] + part8[6][d] + part8[7][d];
                fyr[d] = f;
                fyT_g[d * T + j] = f;              // transposed [e][j]
            }
            __syncthreads();
            // c: 8-way split over e (8 each)
            {
                float s = 0.0f;
                #pragma unroll
                for (int ee = 0; ee < 8; ee++) {
                    int e = p * 8 + ee;
                    s += bk2T_g[e * D + d] * fyr[e];
                }
                part8[p][d] = s;
            }
            __syncthreads();
            if (p == 0)
                c_g[j * D + d] = part8[0][d] + part8[1][d] + part8[2][d] + part8[3][d]
                               + part8[4][d] + part8[5][d] + part8[6][d] + part8[7][d];
        }
        gsync(bar++);

        // ---- phase M3 (block h): M3[(j,h)][d] = sum_e W2T[h][e][d] * fy[j][e] ----
        // one pass over all 128 j; 4x4 register tile; float4 on both operands.
        {
            int h = bid;
            float* w2s  = sbuf;            // [e][d]  4096
            float* fyTs = sbuf + 4096;     // [e][j]  8192
            #pragma unroll
            for (int r = 0; r < 8; r++)
                w2s[tid + r * 512] = W2T_g[h * DD + tid + r * 512];
            #pragma unroll
            for (int r = 0; r < 16; r++)
                fyTs[tid + r * 512] = __ldcg(&fyT_g[tid + r * 512]);
            __syncthreads();
            int tx = tid & 15, ty = tid >> 4;   // tx: 4 d, ty: 4 j (32*4=128)
            float acc[4][4] = {};
            #pragma unroll
            for (int e = 0; e < D; e++) {
                float4 wv = *(const float4*)&w2s[e * 64 + tx * 4];
                float4 fv = *(const float4*)&fyTs[e * 128 + ty * 4];
                acc[0][0] += fv.x * wv.x; acc[0][1] += fv.x * wv.y;
                acc[0][2] += fv.x * wv.z; acc[0][3] += fv.x * wv.w;
                acc[1][0] += fv.y * wv.x; acc[1][1] += fv.y * wv.y;
                acc[1][2] += fv.y * wv.z; acc[1][3] += fv.y * wv.w;
                acc[2][0] += fv.z * wv.x; acc[2][1] += fv.z * wv.y;
                acc[2][2] += fv.z * wv.z; acc[2][3] += fv.z * wv.w;
                acc[3][0] += fv.w * wv.x; acc[3][1] += fv.w * wv.y;
                acc[3][2] += fv.w * wv.z; acc[3][3] += fv.w * wv.w;
            }
            #pragma unroll
            for (int jl = 0; jl < 4; jl++) {
                int j = ty * 4 + jl;
                float4 o = make_float4(acc[jl][0], acc[jl][1], acc[jl][2], acc[jl][3]);
                __stcg((float4*)&M3_g[(j * HK + h) * D + tx * 4], o);
            }
        }
        gsync(bar++);

        // ---- phase G (block b): tasks (j=b, h[0:64)) + (j=127-b, h[64:128)) ----
        // one 128i x 64d acc per block; K-chunk 16; coalesced AT staging.
        {
            float* As = sbuf;            // [hh][i] 16x128
            float* Bs = sbuf + 2048;     // [hh][d] 16x64
            int tx = tid & 15, ty = tid >> 4;   // 4 d cols, 4 i rows per thread
            float acc[4][4] = {};
            int sh = tid >> 5;            // 0..15: h row for As staging
            int si = (tid & 31) * 4;      // 4 consecutive i
            #pragma unroll
            for (int task = 0; task < 2; task++) {
                int j = task ? (127 - bid) : bid;
                int jbase = j * HK + task * 64;
                bool active = (ty * 4 + 3) >= j;
                #pragma unroll
                for (int kb = 0; kb < 4; kb++) {
                    __syncthreads();
                    // As: 16 h-rows x 128 i, coalesced float4 from AT
                    float4 av = *(const float4*)&AT_g[(jbase + kb * 16 + sh) * T + si];
                    *(float4*)&As[sh * 128 + si] = av;
                    // Bs: 16 rows x 64 d contiguous
                    ((float2*)Bs)[tid] = __ldcg(((const float2*)&M3_g[(jbase + kb * 16) * D]) + tid);
                    __syncthreads();
                    if (active) {
                        #pragma unroll
                        for (int hh = 0; hh < 16; hh++) {
                            float4 a = *(const float4*)&As[hh * 128 + ty * 4];
                            float4 b = *(const float4*)&Bs[hh * 64 + tx * 4];
                            acc[0][0] += a.x * b.x; acc[0][1] += a.x * b.y;
                            acc[0][2] += a.x * b.z; acc[0][3] += a.x * b.w;
                            acc[1][0] += a.y * b.x; acc[1][1] += a.y * b.y;
                            acc[1][2] += a.y * b.z; acc[1][3] += a.y * b.w;
                            acc[2][0] += a.z * b.x; acc[2][1] += a.z * b.y;
                            acc[2][2] += a.z * b.z; acc[2][3] += a.z * b.w;
                            acc[3][0] += a.w * b.x; acc[3][1] += a.w * b.y;
                            acc[3][2] += a.w * b.z; acc[3][3] += a.w * b.w;
                        }
                    }
                }
            }
            int minj = min(bid, 127 - bid);
            if (ty * 4 + 3 >= minj) {
                float* gp = &Gpart_g[bid * (T * D)];
                #pragma unroll
                for (int r = 0; r < 4; r++) {
                    float4 o = make_float4(acc[r][0], acc[r][1], acc[r][2], acc[r][3]);
                    *(float4*)&gp[(ty * 4 + r) * D + tx * 4] = o;
                }
            }
        }
        gsync(bar++);

        // ---- phase R (block i): reduce partials (skip known-zero slots) + bias ----
        {
            int i = bid;
            int d = tid & 63, p = tid >> 6;
            float s = 0.0f;
            for (int slot = p; slot < NB; slot += 8) {
                int mn = min(slot, 127 - slot);
                if (mn <= i)
                    s += __ldcg(&Gpart_g[slot * (T * D) + i * D + d]);
            }
            for (int j = p; j <= i; j += 8)
                s += wfun(i, j, dt) * __ldcg(&c_g[j * D + d]);
            part8[p][d] = s;
            __syncthreads();
            if (p == 0)
                G_g[i * D + d] = part8[0][d] + part8[1][d] + part8[2][d] + part8[3][d]
                               + part8[4][d] + part8[5][d] + part8[6][d] + part8[7][d];
        }
        gsync(bar++);
    }

    // ---- tail: block 127 computes out = y0 + (w@G)_{127} ----
    if (bid == T - 1) {
        int d = tid & 63, p = tid >> 6;
        float s = 0.0f;
        for (int i = p; i < T; i += 8)
            s += wfun(T - 1, i, dt) * __ldcg(&G_g[i * D + d]);
        part8[p][d] = s;
        __syncthreads();
        if (p == 0)
            out[d] = z0[d] + part8[0][d] + part8[1][d] + part8[2][d] + part8[3][d]
                           + part8[4][d] + part8[5][d] + part8[6][d] + part8[7][d];
    }
}

extern "C" void kernel_launch(void* const* d_in, const int* in_sizes, int n_in,
                              void* d_out, int out_size) {
    const float* z0  = (const float*)d_in[0];
    const float* t   = (const float*)d_in[1];
    const float* W1  = (const float*)d_in[2];
    const float* b1  = (const float*)d_in[3];
    const float* W2  = (const float*)d_in[4];
    const float* b2  = (const float*)d_in[5];
    const float* Wk1 = (const float*)d_in[6];
    const float* bk1 = (const float*)d_in[7];
    const float* Wk2 = (const float*)d_in[8];
    const float* bk2 = (const float*)d_in[9];
    float* out = (float*)d_out;

    static int attr_done = 0;
    if (!attr_done) {
        cudaFuncSetAttribute(mega, cudaFuncAttributeMaxDynamicSharedMemorySize, 64 * 1024);
        attr_done = 1;
    }
    mega<<<NB, NT, 49152>>>(z0, t, W1, b1, W2, b2, Wk1, bk1, Wk2, bk2, out);
}